// round 1
// baseline (speedup 1.0000x reference)
#include <cuda_runtime.h>
#include <cuda_bf16.h>

// out[b,e] = sum_{o=0..4} tanh( sum_d his[b,d]^(o+1) * ad[b, d*64+e] )
// B=16384, D=64. Pure HBM stream over ad (256 MB, read once).
//
// Layout: 256 threads/block = 16 batch rows/block, 16 threads per row.
// Thread lane (0..15) owns 4 consecutive output columns via float4 loads of
// each W row (d-major): addr = ad + b*4096 + d*64 + lane*4 -> 256B/row/d,
// coalesced. h[d] broadcast from smem; powers h^1..h^5 built with 4 FMULs.

#define ROWS_PER_BLOCK 16
#define NTHREADS 256
#define D 64
#define ORDERS 5

__global__ void __launch_bounds__(NTHREADS)
poly_gemv_tanh_kernel(const float* __restrict__ his,
                      const float* __restrict__ ad,
                      float* __restrict__ out,
                      int B)
{
    __shared__ float sh[ROWS_PER_BLOCK][D];

    const int row0 = blockIdx.x * ROWS_PER_BLOCK;

    // Cooperative coalesced load of the 16 h-vectors (1024 floats).
    #pragma unroll
    for (int i = threadIdx.x; i < ROWS_PER_BLOCK * D; i += NTHREADS) {
        int gr = row0 + (i >> 6);
        sh[i >> 6][i & 63] = (gr < B) ? his[(size_t)gr * D + (i & 63)] : 0.0f;
    }
    __syncthreads();

    const int lane = threadIdx.x & 15;   // which group of 4 output cols
    const int r    = threadIdx.x >> 4;   // which batch row in this block
    const int brow = row0 + r;
    if (brow >= B) return;

    const float4* __restrict__ w4 =
        reinterpret_cast<const float4*>(ad + (size_t)brow * (D * D)) + lane;

    float acc[ORDERS][4];
    #pragma unroll
    for (int o = 0; o < ORDERS; ++o)
        #pragma unroll
        for (int j = 0; j < 4; ++j)
            acc[o][j] = 0.0f;

    #pragma unroll 8
    for (int d = 0; d < D; ++d) {
        const float h = sh[r][d];
        const float4 w = __ldg(w4 + d * 16);   // 16 float4 per W row
        float hp = h;
        #pragma unroll
        for (int o = 0; o < ORDERS; ++o) {
            acc[o][0] = fmaf(hp, w.x, acc[o][0]);
            acc[o][1] = fmaf(hp, w.y, acc[o][1]);
            acc[o][2] = fmaf(hp, w.z, acc[o][2]);
            acc[o][3] = fmaf(hp, w.w, acc[o][3]);
            hp *= h;   // next power (last one dead-code eliminated)
        }
    }

    float4 res;
    res.x = 0.0f; res.y = 0.0f; res.z = 0.0f; res.w = 0.0f;
    #pragma unroll
    for (int o = 0; o < ORDERS; ++o) {
        res.x += tanhf(acc[o][0]);
        res.y += tanhf(acc[o][1]);
        res.z += tanhf(acc[o][2]);
        res.w += tanhf(acc[o][3]);
    }

    reinterpret_cast<float4*>(out + (size_t)brow * D)[lane] = res;
}

extern "C" void kernel_launch(void* const* d_in, const int* in_sizes, int n_in,
                              void* d_out, int out_size)
{
    const float* his = (const float*)d_in[0];   // [B, 64]
    const float* ad  = (const float*)d_in[1];   // [B, 4096]
    float* out       = (float*)d_out;           // [B, 64]

    const int B = in_sizes[0] / D;
    const int grid = (B + ROWS_PER_BLOCK - 1) / ROWS_PER_BLOCK;

    poly_gemv_tanh_kernel<<<grid, NTHREADS>>>(his, ad, out, B);
}

// round 3
// speedup vs baseline: 1.0125x; 1.0125x over previous
#include <cuda_runtime.h>
#include <cuda_bf16.h>

// out[b,e] = sum_{o=0..4} tanh( sum_d his[b,d]^(o+1) * ad[b, d*64+e] )
// B=16384, D=64. Pure HBM stream over ad (256 MB, read once).
//
// Layout: 256 threads/block = 16 batch rows/block, 16 threads per row.
// Thread lane (0..15) owns 4 consecutive output columns via float4 loads of
// each W row (d-major): addr = ad + b*4096 + d*64 + lane*4 -> 256B/row/d,
// coalesced. h[d] broadcast from smem; powers h^1..h^5 built with 4 FMULs.

#define ROWS_PER_BLOCK 16
#define NTHREADS 256
#define D 64
#define ORDERS 5

__global__ void __launch_bounds__(NTHREADS)
poly_gemv_tanh_kernel(const float* __restrict__ his,
                      const float* __restrict__ ad,
                      float* __restrict__ out,
                      int B)
{
    __shared__ float sh[ROWS_PER_BLOCK][D];

    const int row0 = blockIdx.x * ROWS_PER_BLOCK;

    // Cooperative coalesced load of the 16 h-vectors (1024 floats).
    #pragma unroll
    for (int i = threadIdx.x; i < ROWS_PER_BLOCK * D; i += NTHREADS) {
        int gr = row0 + (i >> 6);
        sh[i >> 6][i & 63] = (gr < B) ? his[(size_t)gr * D + (i & 63)] : 0.0f;
    }
    __syncthreads();

    const int lane = threadIdx.x & 15;   // which group of 4 output cols
    const int r    = threadIdx.x >> 4;   // which batch row in this block
    const int brow = row0 + r;
    if (brow >= B) return;

    const float4* __restrict__ w4 =
        reinterpret_cast<const float4*>(ad + (size_t)brow * (D * D)) + lane;

    float acc[ORDERS][4];
    #pragma unroll
    for (int o = 0; o < ORDERS; ++o)
        #pragma unroll
        for (int j = 0; j < 4; ++j)
            acc[o][j] = 0.0f;

    #pragma unroll 8
    for (int d = 0; d < D; ++d) {
        const float h = sh[r][d];
        const float4 w = __ldg(w4 + d * 16);   // 16 float4 per W row
        float hp = h;
        #pragma unroll
        for (int o = 0; o < ORDERS; ++o) {
            acc[o][0] = fmaf(hp, w.x, acc[o][0]);
            acc[o][1] = fmaf(hp, w.y, acc[o][1]);
            acc[o][2] = fmaf(hp, w.z, acc[o][2]);
            acc[o][3] = fmaf(hp, w.w, acc[o][3]);
            hp *= h;   // next power (last one dead-code eliminated)
        }
    }

    float4 res;
    res.x = 0.0f; res.y = 0.0f; res.z = 0.0f; res.w = 0.0f;
    #pragma unroll
    for (int o = 0; o < ORDERS; ++o) {
        res.x += tanhf(acc[o][0]);
        res.y += tanhf(acc[o][1]);
        res.z += tanhf(acc[o][2]);
        res.w += tanhf(acc[o][3]);
    }

    reinterpret_cast<float4*>(out + (size_t)brow * D)[lane] = res;
}

extern "C" void kernel_launch(void* const* d_in, const int* in_sizes, int n_in,
                              void* d_out, int out_size)
{
    const float* his = (const float*)d_in[0];   // [B, 64]
    const float* ad  = (const float*)d_in[1];   // [B, 4096]
    float* out       = (float*)d_out;           // [B, 64]

    const int B = in_sizes[0] / D;
    const int grid = (B + ROWS_PER_BLOCK - 1) / ROWS_PER_BLOCK;

    poly_gemv_tanh_kernel<<<grid, NTHREADS>>>(his, ad, out, B);
}